// round 11
// baseline (speedup 1.0000x reference)
#include <cuda_runtime.h>
#include <cuda_fp16.h>
#include <math.h>
#include <stdint.h>

#define SS 512
#define BB 256
#define DD 256
#define NROWS (SS*BB)          // 131072
#define JROWS ((SS-2)*BB)      // 130560

// ---------------- scratch ----------------
__device__ __align__(256) __half g_src[(size_t)NROWS*DD];
__device__ __align__(256) __half g_h[(size_t)NROWS*DD];
__device__ __align__(256) __half g_p[(size_t)NROWS*512];      // [P1 | P2] per row
__device__ __align__(256) __half g_inn[(size_t)3*JROWS*DD];   // inner1..3
__device__ __align__(256) __half g_mw[DD*DD];
__device__ __align__(256) __half g_ws[512*DD];                // stacked [W1; W2], ld=256

// ---------------- helpers ----------------
__device__ __forceinline__ uint32_t smem_u32(const void* p) {
    uint32_t r;
    asm("{ .reg .u64 t; cvta.to.shared.u64 t, %1; cvt.u32.u64 %0, t; }" : "=r"(r) : "l"(p));
    return r;
}
__device__ __forceinline__ void cp16(uint32_t dst, const void* src) {
    asm volatile("cp.async.cg.shared.global [%0], [%1], 16;" :: "r"(dst), "l"(src));
}
__device__ __forceinline__ void ldmx4(uint32_t* r, uint32_t addr) {
    asm volatile("ldmatrix.sync.aligned.m8n8.x4.shared.b16 {%0,%1,%2,%3}, [%4];"
                 : "=r"(r[0]), "=r"(r[1]), "=r"(r[2]), "=r"(r[3]) : "r"(addr));
}
__device__ __forceinline__ void mma16816(float* d, const uint32_t* a, uint32_t b0, uint32_t b1) {
    asm volatile("mma.sync.aligned.m16n8k16.row.col.f32.f16.f16.f32 "
                 "{%0,%1,%2,%3}, {%4,%5,%6,%7}, {%8,%9}, {%0,%1,%2,%3};"
                 : "+f"(d[0]), "+f"(d[1]), "+f"(d[2]), "+f"(d[3])
                 : "r"(a[0]), "r"(a[1]), "r"(a[2]), "r"(a[3]), "r"(b0), "r"(b1));
}
__device__ __forceinline__ float gelu_f(float x) {
    return 0.5f * x * (1.0f + erff(x * 0.7071067811865476f));
}
// swizzled offset within a 128-row x 64-col fp16 tile (128B rows, 8 x 16B chunks)
__device__ __forceinline__ uint32_t swz(int r, int c) {
    return (uint32_t)(r * 128 + ((c ^ (r & 7)) * 16));
}

// ---------------- fp32 -> fp16 ----------------
__global__ void conv_k(const float* __restrict__ in, __half* __restrict__ o, int n) {
    int i = (blockIdx.x * blockDim.x + threadIdx.x) * 4;
    if (i >= n) return;
    float4 v = *(const float4*)(in + i);
    __half2 t;
    t.x = __float2half(v.x); t.y = __float2half(v.y); *(__half2*)(o + i)     = t;
    t.x = __float2half(v.z); t.y = __float2half(v.w); *(__half2*)(o + i + 2) = t;
}
// stacked weights: ws[j,k] = j<256 ? bl_w[j,k] : bl_w[j-256, 256+k]  (fp16, ld=256)
__global__ void wstack_k(const float* __restrict__ blw, __half* __restrict__ ws) {
    int i = blockIdx.x * 256 + threadIdx.x;   // 0 .. 512*256-1
    int j = i >> 8, k = i & 255;
    float v = (j < 256) ? blw[j * 512 + k] : blw[(j - 256) * 512 + 256 + k];
    ws[i] = __float2half(v);
}

// ---------------- mma.sync GEMM (K = 256) ----------------
// MODE 0: outh[row*ldo + col] = fp16(gelu(acc + bias))
// MODE 3: outh[row*ldo + col] = fp16(acc)           (raw, no bias)
#define NSTG 3
#define STGB 32768            // A 16K + W 16K per stage
#define SMEM_BYTES (1024 + NSTG*STGB)

template<int MODE>
__global__ void __launch_bounds__(256, 2) mma_gemm(
    const __half* __restrict__ A,
    const __half* __restrict__ w,
    const float* __restrict__ bias,
    __half* __restrict__ outh, int ldo)
{
    constexpr int NCH = 4;
    extern __shared__ char smraw[];
    const uint32_t TIL = (smem_u32(smraw) + 1023u) & ~1023u;

    const int tid  = threadIdx.x;
    const int wid  = tid >> 5;
    const int lane = tid & 31;
    const int wm   = wid & 3;
    const int wn   = wid >> 2;
    const int mbase = blockIdx.x * 128;
    const int nbase = blockIdx.y * 128;

    uint32_t aoffs[4][2], woffs[4][4];
    #pragma unroll
    for (int kh = 0; kh < 4; kh++) {
        const int c0 = kh * 2;
        #pragma unroll
        for (int mf = 0; mf < 2; mf++) {
            int r  = wm * 32 + mf * 16 + (lane & 15);
            int cc = c0 + (lane >> 4);
            aoffs[kh][mf] = swz(r, cc);
        }
        #pragma unroll
        for (int nb = 0; nb < 4; nb++) {
            int r  = wn * 64 + nb * 16 + (lane & 7) + ((lane >> 4) << 3);
            int cc = c0 + ((lane >> 3) & 1);
            woffs[kh][nb] = 16384u + swz(r, cc);
        }
    }

    float acc[2][8][4];
    #pragma unroll
    for (int i = 0; i < 2; i++)
        #pragma unroll
        for (int j = 0; j < 8; j++)
            #pragma unroll
            for (int k = 0; k < 4; k++) acc[i][j][k] = 0.f;

    const int lr = tid >> 3;
    const int lc = tid & 7;
    auto load_chunk = [&](int c, int stg) {
        const int k = c * 64;
        const uint32_t sb = TIL + (uint32_t)stg * STGB;
        #pragma unroll
        for (int rep = 0; rep < 4; rep++) {
            int r = lr + rep * 32;
            cp16(sb + swz(r, lc), A + (size_t)(mbase + r) * 256 + k + lc * 8);
        }
        #pragma unroll
        for (int rep = 0; rep < 4; rep++) {
            int r = lr + rep * 32;
            cp16(sb + 16384u + swz(r, lc), w + (size_t)(nbase + r) * 256 + k + lc * 8);
        }
        asm volatile("cp.async.commit_group;" ::: "memory");
    };

    load_chunk(0, 0);
    load_chunk(1, 1);

    #pragma unroll
    for (int c = 0; c < NCH; ++c) {
        if (c == NCH - 1) asm volatile("cp.async.wait_group 0;" ::: "memory");
        else              asm volatile("cp.async.wait_group 1;" ::: "memory");
        __syncthreads();
        if (c + 2 < NCH) load_chunk(c + 2, (c + 2) % NSTG);

        const uint32_t sA = TIL + (uint32_t)(c % NSTG) * STGB;
        #pragma unroll
        for (int kh = 0; kh < 4; kh++) {
            uint32_t a[2][4];
            #pragma unroll
            for (int mf = 0; mf < 2; mf++)
                ldmx4(a[mf], sA + aoffs[kh][mf]);
            uint32_t b[8][2];
            #pragma unroll
            for (int nb = 0; nb < 4; nb++) {
                uint32_t t4[4];
                ldmx4(t4, sA + woffs[kh][nb]);
                b[2 * nb][0] = t4[0];     b[2 * nb][1] = t4[1];
                b[2 * nb + 1][0] = t4[2]; b[2 * nb + 1][1] = t4[3];
            }
            #pragma unroll
            for (int mf = 0; mf < 2; mf++)
                #pragma unroll
                for (int nf = 0; nf < 8; nf++)
                    mma16816(acc[mf][nf], a[mf], b[nf][0], b[nf][1]);
        }
    }

    float2 bn[8];
    if (MODE == 0) {
        #pragma unroll
        for (int nf = 0; nf < 8; nf++) {
            int col = nbase + wn * 64 + nf * 8 + (lane & 3) * 2;
            bn[nf].x = bias[col];
            bn[nf].y = bias[col + 1];
        }
    }

    #pragma unroll
    for (int mf = 0; mf < 2; mf++) {
        #pragma unroll
        for (int half = 0; half < 2; half++) {
            const int row = mbase + wm * 32 + mf * 16 + (lane >> 2) + half * 8;
            const int colb = nbase + wn * 64 + (lane & 3) * 2;
            #pragma unroll
            for (int nf = 0; nf < 8; nf++) {
                const int col = colb + nf * 8;
                float v0 = acc[mf][nf][half * 2 + 0];
                float v1 = acc[mf][nf][half * 2 + 1];
                __half2 hv;
                if (MODE == 0) {
                    hv.x = __float2half(gelu_f(v0 + bn[nf].x));
                    hv.y = __float2half(gelu_f(v1 + bn[nf].y));
                } else {
                    hv.x = __float2half(v0);
                    hv.y = __float2half(v1);
                }
                *reinterpret_cast<__half2*>(outh + (size_t)row * ldo + col) = hv;
            }
        }
    }
}

// ---------------- merged Q kernel: 3 terms, one output tile ----------------
// term 0: out[(row+2BB)*256+col]  = gelu( inn_0[row] @ W2^T + bias + P1[row*512+col] )
// term t: out[(row+2BB)*256+col] += gelu( inn_t[row] @ W2^T + bias + P1[(row+t*BB)*512+col] )
__global__ void __launch_bounds__(256, 2) qmerge_k(
    const __half* __restrict__ inn,
    const __half* __restrict__ w2,
    const float* __restrict__ bias,
    float* __restrict__ outf,
    const __half* __restrict__ P)
{
    extern __shared__ char smraw[];
    const uint32_t TIL = (smem_u32(smraw) + 1023u) & ~1023u;

    const int tid  = threadIdx.x;
    const int wid  = tid >> 5;
    const int lane = tid & 31;
    const int wm   = wid & 3;
    const int wn   = wid >> 2;
    const int mbase = blockIdx.x * 128;
    const int nbase = blockIdx.y * 128;

    uint32_t aoffs[4][2], woffs[4][4];
    #pragma unroll
    for (int kh = 0; kh < 4; kh++) {
        const int c0 = kh * 2;
        #pragma unroll
        for (int mf = 0; mf < 2; mf++) {
            int r  = wm * 32 + mf * 16 + (lane & 15);
            int cc = c0 + (lane >> 4);
            aoffs[kh][mf] = swz(r, cc);
        }
        #pragma unroll
        for (int nb = 0; nb < 4; nb++) {
            int r  = wn * 64 + nb * 16 + (lane & 7) + ((lane >> 4) << 3);
            int cc = c0 + ((lane >> 3) & 1);
            woffs[kh][nb] = 16384u + swz(r, cc);
        }
    }

    float acc[2][8][4];
    #pragma unroll
    for (int i = 0; i < 2; i++)
        #pragma unroll
        for (int j = 0; j < 8; j++)
            #pragma unroll
            for (int k = 0; k < 4; k++) acc[i][j][k] = 0.f;

    float2 bn[8];
    #pragma unroll
    for (int nf = 0; nf < 8; nf++) {
        int col = nbase + wn * 64 + nf * 8 + (lane & 3) * 2;
        bn[nf].x = bias[col];
        bn[nf].y = bias[col + 1];
    }

    const int lr = tid >> 3;
    const int lc = tid & 7;
    auto load_chunk = [&](int q, int stg) {
        const int term = q >> 2;
        const int k = (q & 3) * 64;
        const __half* A = inn + (size_t)term * JROWS * 256;
        const uint32_t sb = TIL + (uint32_t)stg * STGB;
        #pragma unroll
        for (int rep = 0; rep < 4; rep++) {
            int r = lr + rep * 32;
            cp16(sb + swz(r, lc), A + (size_t)(mbase + r) * 256 + k + lc * 8);
        }
        #pragma unroll
        for (int rep = 0; rep < 4; rep++) {
            int r = lr + rep * 32;
            cp16(sb + 16384u + swz(r, lc), w2 + (size_t)(nbase + r) * 256 + k + lc * 8);
        }
        asm volatile("cp.async.commit_group;" ::: "memory");
    };

    load_chunk(0, 0);
    load_chunk(1, 1);

    #pragma unroll
    for (int q = 0; q < 12; ++q) {
        if (q == 11) asm volatile("cp.async.wait_group 0;" ::: "memory");
        else         asm volatile("cp.async.wait_group 1;" ::: "memory");
        __syncthreads();
        if (q + 2 < 12) load_chunk(q + 2, (q + 2) % NSTG);

        const uint32_t sA = TIL + (uint32_t)(q % NSTG) * STGB;
        #pragma unroll
        for (int kh = 0; kh < 4; kh++) {
            uint32_t a[2][4];
            #pragma unroll
            for (int mf = 0; mf < 2; mf++)
                ldmx4(a[mf], sA + aoffs[kh][mf]);
            uint32_t b[8][2];
            #pragma unroll
            for (int nb = 0; nb < 4; nb++) {
                uint32_t t4[4];
                ldmx4(t4, sA + woffs[kh][nb]);
                b[2 * nb][0] = t4[0];     b[2 * nb][1] = t4[1];
                b[2 * nb + 1][0] = t4[2]; b[2 * nb + 1][1] = t4[3];
            }
            #pragma unroll
            for (int mf = 0; mf < 2; mf++)
                #pragma unroll
                for (int nf = 0; nf < 8; nf++)
                    mma16816(acc[mf][nf], a[mf], b[nf][0], b[nf][1]);
        }

        if ((q & 3) == 3) {
            const int term = q >> 2;
            const int p1shift = term * BB;
            #pragma unroll
            for (int mf = 0; mf < 2; mf++) {
                #pragma unroll
                for (int half = 0; half < 2; half++) {
                    const int row = mbase + wm * 32 + mf * 16 + (lane >> 2) + half * 8;
                    const int colb = nbase + wn * 64 + (lane & 3) * 2;
                    #pragma unroll
                    for (int nf = 0; nf < 8; nf++) {
                        const int col = colb + nf * 8;
                        __half2 p1v = *reinterpret_cast<const __half2*>(
                            P + (size_t)(row + p1shift) * 512 + col);
                        float g0 = gelu_f(acc[mf][nf][half * 2 + 0] + bn[nf].x + __half2float(p1v.x));
                        float g1 = gelu_f(acc[mf][nf][half * 2 + 1] + bn[nf].y + __half2float(p1v.y));
                        const size_t ob = (size_t)(row + 2 * BB) * DD + col;
                        float2 o;
                        if (term == 0) { o.x = g0; o.y = g1; }
                        else {
                            o = *reinterpret_cast<float2*>(outf + ob);
                            o.x += g0; o.y += g1;
                        }
                        *reinterpret_cast<float2*>(outf + ob) = o;
                        acc[mf][nf][half * 2 + 0] = 0.f;
                        acc[mf][nf][half * 2 + 1] = 0.f;
                    }
                }
            }
        }
    }
}

// ---------------- inner blackets only, 8-step s-window ----------------
// inner1[r] = gelu(P1[r+BB]  + P2[r+2BB] + bb)   (r = s*BB+rb, s <= SS-3)
// inner2[r] = gelu(P1[r+2BB] + P2[r]     + bb)
// inner3[r] = gelu(P1[r]     + P2[r+BB]  + bb)
__global__ void ew_inner_k(const __half* __restrict__ P, const float* __restrict__ bb,
                           __half* __restrict__ inn)
{
    const int gtid = blockIdx.x * 256 + threadIdx.x;   // 64*256*128 = 2,097,152
    const int cp = gtid & 127;
    const int rb = (gtid >> 7) & 255;
    const int sc = gtid >> 15;                         // s-chunk 0..63
    const int s0 = sc * 8;
    const int c  = cp * 2;
    const float b0 = bb[c], b1 = bb[c + 1];

    const size_t pstep = (size_t)BB * 512;
    const __half2* P1p = (const __half2*)(P + (size_t)rb * 512 + c);
    const __half2* P2p = (const __half2*)(P + (size_t)rb * 512 + 256 + c);

    __half2 p1w[10], p2w[10];
    #pragma unroll
    for (int j = 0; j < 10; j++) {
        int s = s0 + j;
        if (s < SS) {
            p1w[j] = P1p[(size_t)s * (pstep / 2)];
            p2w[j] = P2p[(size_t)s * (pstep / 2)];
        } else {
            p1w[j] = __half2half2(__float2half(0.f));
            p2w[j] = __half2half2(__float2half(0.f));
        }
    }

    const size_t dstep = (size_t)BB * DD;
    __half* i1p = inn + (size_t)rb * DD + c;
    __half* i2p = i1p + (size_t)JROWS * DD;
    __half* i3p = i2p + (size_t)JROWS * DD;

    #pragma unroll
    for (int i = 0; i < 8; i++) {
        const int s = s0 + i;
        if (s > SS - 3) break;
        const size_t ib = (size_t)s * dstep;
        __half2 o;
        float2 a, b;
        // inner1: P1[s+1] + P2[s+2]
        a = __half22float2(p1w[i + 1]); b = __half22float2(p2w[i + 2]);
        o.x = __float2half(gelu_f(a.x + b.x + b0));
        o.y = __float2half(gelu_f(a.y + b.y + b1));
        *(__half2*)(i1p + ib) = o;
        // inner2: P1[s+2] + P2[s]
        a = __half22float2(p1w[i + 2]); b = __half22float2(p2w[i]);
        o.x = __float2half(gelu_f(a.x + b.x + b0));
        o.y = __float2half(gelu_f(a.y + b.y + b1));
        *(__half2*)(i2p + ib) = o;
        // inner3: P1[s] + P2[s+1]
        a = __half22float2(p1w[i]); b = __half22float2(p2w[i + 1]);
        o.x = __float2half(gelu_f(a.x + b.x + b0));
        o.y = __float2half(gelu_f(a.y + b.y + b1));
        *(__half2*)(i3p + ib) = o;
    }
}

// ---------------- cumsum with inline delta ----------------
// total(s) = delta(s) + (s>=2 ? J[s] : 0),  out[s] = running sum
// delta(s) = (s>0 ? h[s-1] + gelu(P1[s-1] + P2[s] + bb) : gelu(P2[0] + bb))
__global__ void cumsum_k(const __half* __restrict__ P, const __half* __restrict__ h,
                         const float* __restrict__ bb, float* __restrict__ out)
{
    const int id = blockIdx.x * 256 + threadIdx.x;   // 65536 threads
    const int c  = id & 255;
    const int rb = id >> 8;
    const float b = bb[c];

    const size_t pstep = (size_t)BB * 512;
    const size_t dstep = (size_t)BB * DD;
    const __half* P1p = P + (size_t)rb * 512 + c;
    const __half* P2p = P1p + 256;
    const __half* hp  = h + (size_t)rb * DD + c;
    float*        op  = out + (size_t)rb * DD + c;

    float run = 0.f;
    float p1prev = 0.f, hprev = 0.f;
    #pragma unroll 4
    for (int s = 0; s < SS; s++) {
        float p2v = __half2float(P2p[(size_t)s * pstep]);
        float t;
        if (s == 0) t = gelu_f(p2v + b);
        else        t = hprev + gelu_f(p1prev + p2v + b);
        if (s >= 2) t += op[(size_t)s * dstep];
        run += t;
        op[(size_t)s * dstep] = run;
        // prep next
        p1prev = __half2float(P1p[(size_t)s * pstep]);
        hprev  = __half2float(hp[(size_t)s * dstep]);
    }
}

extern "C" void kernel_launch(void* const* d_in, const int* in_sizes, int n_in,
                              void* d_out, int out_size)
{
    const float* src = nullptr; const float* map_w = nullptr; const float* bl_w = nullptr;
    const float* map_b = nullptr; const float* bl_b = nullptr;
    for (int i = 0; i < n_in; i++) {
        if (in_sizes[i] == NROWS * DD)       src   = (const float*)d_in[i];
        else if (in_sizes[i] == DD * DD)     map_w = (const float*)d_in[i];
        else if (in_sizes[i] == DD * 2 * DD) bl_w  = (const float*)d_in[i];
        else if (in_sizes[i] == DD) { if (!map_b) map_b = (const float*)d_in[i]; else bl_b = (const float*)d_in[i]; }
    }
    float* out = (float*)d_out;

    __half *sf, *h, *p, *inn, *mw, *ws;
    cudaGetSymbolAddress((void**)&sf,  g_src);
    cudaGetSymbolAddress((void**)&h,   g_h);
    cudaGetSymbolAddress((void**)&p,   g_p);
    cudaGetSymbolAddress((void**)&inn, g_inn);
    cudaGetSymbolAddress((void**)&mw,  g_mw);
    cudaGetSymbolAddress((void**)&ws,  g_ws);

    cudaFuncSetAttribute(mma_gemm<0>, cudaFuncAttributeMaxDynamicSharedMemorySize, SMEM_BYTES);
    cudaFuncSetAttribute(mma_gemm<3>, cudaFuncAttributeMaxDynamicSharedMemorySize, SMEM_BYTES);
    cudaFuncSetAttribute(qmerge_k,    cudaFuncAttributeMaxDynamicSharedMemorySize, SMEM_BYTES);

    conv_k<<<(NROWS * DD / 4 + 255) / 256, 256>>>(src, sf, NROWS * DD);
    conv_k<<<(DD * DD / 4 + 255) / 256, 256>>>(map_w, mw, DD * DD);
    wstack_k<<<512, 256>>>(bl_w, ws);

    const __half* w2 = ws + 256 * 256;   // rows 256..511 of the stack = W2

    // 1) h = gelu(src @ map_w^T + map_b) -> fp16
    mma_gemm<0><<<dim3(NROWS / 128, 2), 256, SMEM_BYTES>>>(sf, mw, map_b, h, DD);
    // 2) P = h @ [W1; W2]^T  (N = 512, raw fp16)
    mma_gemm<3><<<dim3(NROWS / 128, 4), 256, SMEM_BYTES>>>(h, ws, nullptr, p, 512);
    // 3) 3 inner blackets (8-step window over s)
    ew_inner_k<<<64 * 256 * 128 / 256, 256>>>(p, bl_b, inn);
    // 4) merged: out[2B:] = / += gelu(inner_t @ W2^T + P1[t*BB shift] + bl_b)
    qmerge_k<<<dim3(JROWS / 128, 2), 256, SMEM_BYTES>>>(inn, w2, bl_b, out, p);
    // 5) cumsum along axis 0 with inline delta
    cumsum_k<<<(BB * DD) / 256, 256>>>(p, h, bl_b, out);
}

// round 12
// speedup vs baseline: 1.3485x; 1.3485x over previous
#include <cuda_runtime.h>
#include <cuda_fp16.h>
#include <math.h>
#include <stdint.h>

#define SS 512
#define BB 256
#define DD 256
#define NROWS (SS*BB)          // 131072
#define JROWS ((SS-2)*BB)      // 130560

// ---------------- scratch ----------------
__device__ __align__(256) __half g_src[(size_t)NROWS*DD];
__device__ __align__(256) __half g_h[(size_t)NROWS*DD];
__device__ __align__(256) __half g_p[(size_t)NROWS*512];      // [P1 | P2] per row
__device__ __align__(256) __half g_inn[(size_t)3*JROWS*DD];   // inner1..3
__device__ __align__(256) __half g_j[(size_t)3*JROWS*DD];     // J term outputs (fp16)
__device__ __align__(256) __half g_mw[DD*DD];
__device__ __align__(256) __half g_ws[512*DD];                // stacked [W1; W2], ld=256

// ---------------- helpers ----------------
__device__ __forceinline__ uint32_t smem_u32(const void* p) {
    uint32_t r;
    asm("{ .reg .u64 t; cvta.to.shared.u64 t, %1; cvt.u32.u64 %0, t; }" : "=r"(r) : "l"(p));
    return r;
}
__device__ __forceinline__ void cp16(uint32_t dst, const void* src) {
    asm volatile("cp.async.cg.shared.global [%0], [%1], 16;" :: "r"(dst), "l"(src));
}
__device__ __forceinline__ void ldmx4(uint32_t* r, uint32_t addr) {
    asm volatile("ldmatrix.sync.aligned.m8n8.x4.shared.b16 {%0,%1,%2,%3}, [%4];"
                 : "=r"(r[0]), "=r"(r[1]), "=r"(r[2]), "=r"(r[3]) : "r"(addr));
}
__device__ __forceinline__ void mma16816(float* d, const uint32_t* a, uint32_t b0, uint32_t b1) {
    asm volatile("mma.sync.aligned.m16n8k16.row.col.f32.f16.f16.f32 "
                 "{%0,%1,%2,%3}, {%4,%5,%6,%7}, {%8,%9}, {%0,%1,%2,%3};"
                 : "+f"(d[0]), "+f"(d[1]), "+f"(d[2]), "+f"(d[3])
                 : "r"(a[0]), "r"(a[1]), "r"(a[2]), "r"(a[3]), "r"(b0), "r"(b1));
}
__device__ __forceinline__ float gelu_f(float x) {
    return 0.5f * x * (1.0f + erff(x * 0.7071067811865476f));
}
// swizzled offset within a 128-row x 64-col fp16 tile (128B rows, 8 x 16B chunks)
__device__ __forceinline__ uint32_t swz(int r, int c) {
    return (uint32_t)(r * 128 + ((c ^ (r & 7)) * 16));
}

// ---------------- fp32 -> fp16 ----------------
__global__ void conv_k(const float* __restrict__ in, __half* __restrict__ o, int n) {
    int i = (blockIdx.x * blockDim.x + threadIdx.x) * 4;
    if (i >= n) return;
    float4 v = *(const float4*)(in + i);
    __half2 t;
    t.x = __float2half(v.x); t.y = __float2half(v.y); *(__half2*)(o + i)     = t;
    t.x = __float2half(v.z); t.y = __float2half(v.w); *(__half2*)(o + i + 2) = t;
}
// stacked weights: ws[j,k] = j<256 ? bl_w[j,k] : bl_w[j-256, 256+k]  (fp16, ld=256)
__global__ void wstack_k(const float* __restrict__ blw, __half* __restrict__ ws) {
    int i = blockIdx.x * 256 + threadIdx.x;   // 0 .. 512*256-1
    int j = i >> 8, k = i & 255;
    float v = (j < 256) ? blw[j * 512 + k] : blw[(j - 256) * 512 + 256 + k];
    ws[i] = __float2half(v);
}

// ---------------- mma.sync GEMM (K = 256) ----------------
// MODE 0: outh[row*ldo + col] = fp16(gelu(acc + bias))
// MODE 3: outh[row*ldo + col] = fp16(acc)           (raw, no bias)
#define NSTG 3
#define STGB 32768            // A 16K + W 16K per stage
#define SMEM_BYTES (1024 + NSTG*STGB)

template<int MODE>
__global__ void __launch_bounds__(256, 2) mma_gemm(
    const __half* __restrict__ A,
    const __half* __restrict__ w,
    const float* __restrict__ bias,
    __half* __restrict__ outh, int ldo)
{
    constexpr int NCH = 4;
    extern __shared__ char smraw[];
    const uint32_t TIL = (smem_u32(smraw) + 1023u) & ~1023u;

    const int tid  = threadIdx.x;
    const int wid  = tid >> 5;
    const int lane = tid & 31;
    const int wm   = wid & 3;
    const int wn   = wid >> 2;
    const int mbase = blockIdx.x * 128;
    const int nbase = blockIdx.y * 128;

    uint32_t aoffs[4][2], woffs[4][4];
    #pragma unroll
    for (int kh = 0; kh < 4; kh++) {
        const int c0 = kh * 2;
        #pragma unroll
        for (int mf = 0; mf < 2; mf++) {
            int r  = wm * 32 + mf * 16 + (lane & 15);
            int cc = c0 + (lane >> 4);
            aoffs[kh][mf] = swz(r, cc);
        }
        #pragma unroll
        for (int nb = 0; nb < 4; nb++) {
            int r  = wn * 64 + nb * 16 + (lane & 7) + ((lane >> 4) << 3);
            int cc = c0 + ((lane >> 3) & 1);
            woffs[kh][nb] = 16384u + swz(r, cc);
        }
    }

    float acc[2][8][4];
    #pragma unroll
    for (int i = 0; i < 2; i++)
        #pragma unroll
        for (int j = 0; j < 8; j++)
            #pragma unroll
            for (int k = 0; k < 4; k++) acc[i][j][k] = 0.f;

    const int lr = tid >> 3;
    const int lc = tid & 7;
    auto load_chunk = [&](int c, int stg) {
        const int k = c * 64;
        const uint32_t sb = TIL + (uint32_t)stg * STGB;
        #pragma unroll
        for (int rep = 0; rep < 4; rep++) {
            int r = lr + rep * 32;
            cp16(sb + swz(r, lc), A + (size_t)(mbase + r) * 256 + k + lc * 8);
        }
        #pragma unroll
        for (int rep = 0; rep < 4; rep++) {
            int r = lr + rep * 32;
            cp16(sb + 16384u + swz(r, lc), w + (size_t)(nbase + r) * 256 + k + lc * 8);
        }
        asm volatile("cp.async.commit_group;" ::: "memory");
    };

    load_chunk(0, 0);
    load_chunk(1, 1);

    #pragma unroll
    for (int c = 0; c < NCH; ++c) {
        if (c == NCH - 1) asm volatile("cp.async.wait_group 0;" ::: "memory");
        else              asm volatile("cp.async.wait_group 1;" ::: "memory");
        __syncthreads();
        if (c + 2 < NCH) load_chunk(c + 2, (c + 2) % NSTG);

        const uint32_t sA = TIL + (uint32_t)(c % NSTG) * STGB;
        #pragma unroll
        for (int kh = 0; kh < 4; kh++) {
            uint32_t a[2][4];
            #pragma unroll
            for (int mf = 0; mf < 2; mf++)
                ldmx4(a[mf], sA + aoffs[kh][mf]);
            uint32_t b[8][2];
            #pragma unroll
            for (int nb = 0; nb < 4; nb++) {
                uint32_t t4[4];
                ldmx4(t4, sA + woffs[kh][nb]);
                b[2 * nb][0] = t4[0];     b[2 * nb][1] = t4[1];
                b[2 * nb + 1][0] = t4[2]; b[2 * nb + 1][1] = t4[3];
            }
            #pragma unroll
            for (int mf = 0; mf < 2; mf++)
                #pragma unroll
                for (int nf = 0; nf < 8; nf++)
                    mma16816(acc[mf][nf], a[mf], b[nf][0], b[nf][1]);
        }
    }

    float2 bn[8];
    if (MODE == 0) {
        #pragma unroll
        for (int nf = 0; nf < 8; nf++) {
            int col = nbase + wn * 64 + nf * 8 + (lane & 3) * 2;
            bn[nf].x = bias[col];
            bn[nf].y = bias[col + 1];
        }
    }

    #pragma unroll
    for (int mf = 0; mf < 2; mf++) {
        #pragma unroll
        for (int half = 0; half < 2; half++) {
            const int row = mbase + wm * 32 + mf * 16 + (lane >> 2) + half * 8;
            const int colb = nbase + wn * 64 + (lane & 3) * 2;
            #pragma unroll
            for (int nf = 0; nf < 8; nf++) {
                const int col = colb + nf * 8;
                float v0 = acc[mf][nf][half * 2 + 0];
                float v1 = acc[mf][nf][half * 2 + 1];
                __half2 hv;
                if (MODE == 0) {
                    hv.x = __float2half(gelu_f(v0 + bn[nf].x));
                    hv.y = __float2half(gelu_f(v1 + bn[nf].y));
                } else {
                    hv.x = __float2half(v0);
                    hv.y = __float2half(v1);
                }
                *reinterpret_cast<__half2*>(outh + (size_t)row * ldo + col) = hv;
            }
        }
    }
}

// ---------------- merged Q kernel: 3 terms -> 3 fp16 J buffers (store-only) ----------------
// term t: gj[t*JROWS*DD + row*256 + col] = fp16(gelu( inn_t[row] @ W2^T + bias
//                                                     + P1[(row + t*BB)*512 + col] ))
__global__ void __launch_bounds__(256, 2) qmerge_k(
    const __half* __restrict__ inn,
    const __half* __restrict__ w2,
    const float* __restrict__ bias,
    __half* __restrict__ gj,
    const __half* __restrict__ P)
{
    extern __shared__ char smraw[];
    const uint32_t TIL = (smem_u32(smraw) + 1023u) & ~1023u;

    const int tid  = threadIdx.x;
    const int wid  = tid >> 5;
    const int lane = tid & 31;
    const int wm   = wid & 3;
    const int wn   = wid >> 2;
    const int mbase = blockIdx.x * 128;
    const int nbase = blockIdx.y * 128;

    uint32_t aoffs[4][2], woffs[4][4];
    #pragma unroll
    for (int kh = 0; kh < 4; kh++) {
        const int c0 = kh * 2;
        #pragma unroll
        for (int mf = 0; mf < 2; mf++) {
            int r  = wm * 32 + mf * 16 + (lane & 15);
            int cc = c0 + (lane >> 4);
            aoffs[kh][mf] = swz(r, cc);
        }
        #pragma unroll
        for (int nb = 0; nb < 4; nb++) {
            int r  = wn * 64 + nb * 16 + (lane & 7) + ((lane >> 4) << 3);
            int cc = c0 + ((lane >> 3) & 1);
            woffs[kh][nb] = 16384u + swz(r, cc);
        }
    }

    float acc[2][8][4];
    #pragma unroll
    for (int i = 0; i < 2; i++)
        #pragma unroll
        for (int j = 0; j < 8; j++)
            #pragma unroll
            for (int k = 0; k < 4; k++) acc[i][j][k] = 0.f;

    float2 bn[8];
    #pragma unroll
    for (int nf = 0; nf < 8; nf++) {
        int col = nbase + wn * 64 + nf * 8 + (lane & 3) * 2;
        bn[nf].x = bias[col];
        bn[nf].y = bias[col + 1];
    }

    const int lr = tid >> 3;
    const int lc = tid & 7;
    auto load_chunk = [&](int q, int stg) {
        const int term = q >> 2;
        const int k = (q & 3) * 64;
        const __half* A = inn + (size_t)term * JROWS * 256;
        const uint32_t sb = TIL + (uint32_t)stg * STGB;
        #pragma unroll
        for (int rep = 0; rep < 4; rep++) {
            int r = lr + rep * 32;
            cp16(sb + swz(r, lc), A + (size_t)(mbase + r) * 256 + k + lc * 8);
        }
        #pragma unroll
        for (int rep = 0; rep < 4; rep++) {
            int r = lr + rep * 32;
            cp16(sb + 16384u + swz(r, lc), w2 + (size_t)(nbase + r) * 256 + k + lc * 8);
        }
        asm volatile("cp.async.commit_group;" ::: "memory");
    };

    load_chunk(0, 0);
    load_chunk(1, 1);

    #pragma unroll
    for (int q = 0; q < 12; ++q) {
        if (q == 11) asm volatile("cp.async.wait_group 0;" ::: "memory");
        else         asm volatile("cp.async.wait_group 1;" ::: "memory");
        __syncthreads();
        if (q + 2 < 12) load_chunk(q + 2, (q + 2) % NSTG);

        const uint32_t sA = TIL + (uint32_t)(q % NSTG) * STGB;
        #pragma unroll
        for (int kh = 0; kh < 4; kh++) {
            uint32_t a[2][4];
            #pragma unroll
            for (int mf = 0; mf < 2; mf++)
                ldmx4(a[mf], sA + aoffs[kh][mf]);
            uint32_t b[8][2];
            #pragma unroll
            for (int nb = 0; nb < 4; nb++) {
                uint32_t t4[4];
                ldmx4(t4, sA + woffs[kh][nb]);
                b[2 * nb][0] = t4[0];     b[2 * nb][1] = t4[1];
                b[2 * nb + 1][0] = t4[2]; b[2 * nb + 1][1] = t4[3];
            }
            #pragma unroll
            for (int mf = 0; mf < 2; mf++)
                #pragma unroll
                for (int nf = 0; nf < 8; nf++)
                    mma16816(acc[mf][nf], a[mf], b[nf][0], b[nf][1]);
        }

        if ((q & 3) == 3) {
            const int term = q >> 2;
            const int p1shift = term * BB;
            __half* jt = gj + (size_t)term * JROWS * DD;
            #pragma unroll
            for (int mf = 0; mf < 2; mf++) {
                #pragma unroll
                for (int half = 0; half < 2; half++) {
                    const int row = mbase + wm * 32 + mf * 16 + (lane >> 2) + half * 8;
                    const int colb = nbase + wn * 64 + (lane & 3) * 2;
                    #pragma unroll
                    for (int nf = 0; nf < 8; nf++) {
                        const int col = colb + nf * 8;
                        __half2 p1v = *reinterpret_cast<const __half2*>(
                            P + (size_t)(row + p1shift) * 512 + col);
                        float g0 = gelu_f(acc[mf][nf][half * 2 + 0] + bn[nf].x + __half2float(p1v.x));
                        float g1 = gelu_f(acc[mf][nf][half * 2 + 1] + bn[nf].y + __half2float(p1v.y));
                        __half2 hv;
                        hv.x = __float2half(g0);
                        hv.y = __float2half(g1);
                        *reinterpret_cast<__half2*>(jt + (size_t)row * DD + col) = hv;
                        acc[mf][nf][half * 2 + 0] = 0.f;
                        acc[mf][nf][half * 2 + 1] = 0.f;
                    }
                }
            }
        }
    }
}

// ---------------- elementwise: delta + 3 inner blackets (R8/R10 style) ----------------
__global__ void ew_k(const __half* __restrict__ P, const __half* __restrict__ h,
                     const float* __restrict__ bb, float* __restrict__ out,
                     __half* __restrict__ inn)
{
    int t = blockIdx.x * 256 + threadIdx.x;   // NROWS*128 threads
    int r = t >> 7;
    int c = (t & 127) * 2;
    float b0 = bb[c], b1 = bb[c + 1];

    __half2 p2r = *(const __half2*)(P + (size_t)r * 512 + 256 + c);
    float p2r0 = __half2float(p2r.x), p2r1 = __half2float(p2r.y);

    float d0, d1;
    if (r >= BB) {
        __half2 p1m = *(const __half2*)(P + (size_t)(r - BB) * 512 + c);
        __half2 hm  = *(const __half2*)(h + (size_t)(r - BB) * DD + c);
        d0 = __half2float(hm.x) + gelu_f(__half2float(p1m.x) + p2r0 + b0);
        d1 = __half2float(hm.y) + gelu_f(__half2float(p1m.y) + p2r1 + b1);
    } else {
        d0 = gelu_f(p2r0 + b0);
        d1 = gelu_f(p2r1 + b1);
    }
    *(float2*)(out + (size_t)r * DD + c) = make_float2(d0, d1);

    if (r < JROWS) {
        __half2 p1_0 = *(const __half2*)(P + (size_t)r * 512 + c);
        __half2 p1_1 = *(const __half2*)(P + (size_t)(r + BB) * 512 + c);
        __half2 p1_2 = *(const __half2*)(P + (size_t)(r + 2 * BB) * 512 + c);
        __half2 p2_1 = *(const __half2*)(P + (size_t)(r + BB) * 512 + 256 + c);
        __half2 p2_2 = *(const __half2*)(P + (size_t)(r + 2 * BB) * 512 + 256 + c);
        __half2 o;
        o.x = __float2half(gelu_f(__half2float(p1_1.x) + __half2float(p2_2.x) + b0));
        o.y = __float2half(gelu_f(__half2float(p1_1.y) + __half2float(p2_2.y) + b1));
        *(__half2*)(inn + (size_t)r * DD + c) = o;
        o.x = __float2half(gelu_f(__half2float(p1_2.x) + p2r0 + b0));
        o.y = __float2half(gelu_f(__half2float(p1_2.y) + p2r1 + b1));
        *(__half2*)(inn + (size_t)JROWS * DD + (size_t)r * DD + c) = o;
        o.x = __float2half(gelu_f(__half2float(p1_0.x) + __half2float(p2_1.x) + b0));
        o.y = __float2half(gelu_f(__half2float(p1_0.y) + __half2float(p2_1.y) + b1));
        *(__half2*)(inn + (size_t)2 * JROWS * DD + (size_t)r * DD + c) = o;
    }
}

// ---------------- cumsum over axis 0 (delta in out, J terms from gj) ----------------
__global__ void cumsum_k(float* __restrict__ out, const __half* __restrict__ gj) {
    const int id = blockIdx.x * 256 + threadIdx.x;   // 65536 threads
    const int c  = id & 255;
    const int rb = id >> 8;
    const size_t dstep = (size_t)BB * DD;
    const __half* j1 = gj + (size_t)rb * DD + c;
    const __half* j2 = j1 + (size_t)JROWS * DD;
    const __half* j3 = j2 + (size_t)JROWS * DD;
    float* op = out + (size_t)rb * DD + c;

    float run = 0.f;
    #pragma unroll 4
    for (int s = 0; s < SS; s++) {
        float t = op[(size_t)s * dstep];
        if (s >= 2) {
            const size_t jb = (size_t)(s - 2) * dstep;
            t += __half2float(j1[jb]) + __half2float(j2[jb]) + __half2float(j3[jb]);
        }
        run += t;
        op[(size_t)s * dstep] = run;
    }
}

extern "C" void kernel_launch(void* const* d_in, const int* in_sizes, int n_in,
                              void* d_out, int out_size)
{
    const float* src = nullptr; const float* map_w = nullptr; const float* bl_w = nullptr;
    const float* map_b = nullptr; const float* bl_b = nullptr;
    for (int i = 0; i < n_in; i++) {
        if (in_sizes[i] == NROWS * DD)       src   = (const float*)d_in[i];
        else if (in_sizes[i] == DD * DD)     map_w = (const float*)d_in[i];
        else if (in_sizes[i] == DD * 2 * DD) bl_w  = (const float*)d_in[i];
        else if (in_sizes[i] == DD) { if (!map_b) map_b = (const float*)d_in[i]; else bl_b = (const float*)d_in[i]; }
    }
    float* out = (float*)d_out;

    __half *sf, *h, *p, *inn, *gj, *mw, *ws;
    cudaGetSymbolAddress((void**)&sf,  g_src);
    cudaGetSymbolAddress((void**)&h,   g_h);
    cudaGetSymbolAddress((void**)&p,   g_p);
    cudaGetSymbolAddress((void**)&inn, g_inn);
    cudaGetSymbolAddress((void**)&gj,  g_j);
    cudaGetSymbolAddress((void**)&mw,  g_mw);
    cudaGetSymbolAddress((void**)&ws,  g_ws);

    cudaFuncSetAttribute(mma_gemm<0>, cudaFuncAttributeMaxDynamicSharedMemorySize, SMEM_BYTES);
    cudaFuncSetAttribute(mma_gemm<3>, cudaFuncAttributeMaxDynamicSharedMemorySize, SMEM_BYTES);
    cudaFuncSetAttribute(qmerge_k,    cudaFuncAttributeMaxDynamicSharedMemorySize, SMEM_BYTES);

    conv_k<<<(NROWS * DD / 4 + 255) / 256, 256>>>(src, sf, NROWS * DD);
    conv_k<<<(DD * DD / 4 + 255) / 256, 256>>>(map_w, mw, DD * DD);
    wstack_k<<<512, 256>>>(bl_w, ws);

    const __half* w2 = ws + 256 * 256;   // rows 256..511 of the stack = W2

    // 1) h = gelu(src @ map_w^T + map_b) -> fp16
    mma_gemm<0><<<dim3(NROWS / 128, 2), 256, SMEM_BYTES>>>(sf, mw, map_b, h, DD);
    // 2) P = h @ [W1; W2]^T  (N = 512, raw fp16)
    mma_gemm<3><<<dim3(NROWS / 128, 4), 256, SMEM_BYTES>>>(h, ws, nullptr, p, 512);
    // 3) delta (-> out) + 3 inner blackets
    ew_k<<<NROWS * 128 / 256, 256>>>(p, h, bl_b, out, inn);
    // 4) J terms -> 3 fp16 buffers (store-only, no RMW)
    qmerge_k<<<dim3(JROWS / 128, 2), 256, SMEM_BYTES>>>(inn, w2, bl_b, gj, p);
    // 5) cumsum along axis 0, folding in J terms
    cumsum_k<<<(BB * DD) / 256, 256>>>(out, gj);
}